// round 14
// baseline (speedup 1.0000x reference)
#include <cuda_runtime.h>
#include <cuda_fp16.h>
#include <math.h>
#include <cstdint>

#define BATCH 8
#define S_LEN 1024
#define DMODEL 1024
#define NHEAD 16
#define DHEAD 64
#define MAXK 4
#define MROWS (BATCH * S_LEN)   // 8192

// Scratch (allocation-free rule -> device globals)
__device__ __half g_act3[(size_t)3 * MROWS * DMODEL];
__device__ __half g_w4[(size_t)4 * DMODEL * DMODEL];
__device__ __half g_qh[(size_t)MROWS * DMODEL];
__device__ __half g_kh[(size_t)MROWS * DMODEL];
__device__ __half g_vh[(size_t)MROWS * DMODEL];
__device__ __half g_oh[(size_t)MROWS * DMODEL];

// ---------------------------------------------------------------------------
__device__ __forceinline__ void mma16816(float* c, const uint32_t* a, const uint32_t* b) {
    asm volatile(
        "mma.sync.aligned.m16n8k16.row.col.f32.f16.f16.f32 "
        "{%0,%1,%2,%3}, {%4,%5,%6,%7}, {%8,%9}, {%0,%1,%2,%3};"
        : "+f"(c[0]), "+f"(c[1]), "+f"(c[2]), "+f"(c[3])
        : "r"(a[0]), "r"(a[1]), "r"(a[2]), "r"(a[3]), "r"(b[0]), "r"(b[1]));
}
__device__ __forceinline__ uint32_t pack_h(float x, float y) {
    __half2 t = __floats2half2_rn(x, y);
    return *(uint32_t*)&t;
}
__device__ __forceinline__ uint32_t smem_u32(const void* p) {
    uint32_t a;
    asm("{ .reg .u64 t; cvta.to.shared.u64 t, %1; cvt.u32.u64 %0, t; }"
        : "=r"(a) : "l"(p));
    return a;
}
__device__ __forceinline__ void ldmx4(uint32_t* r, uint32_t addr) {
    asm volatile("ldmatrix.sync.aligned.m8n8.x4.shared.b16 {%0,%1,%2,%3}, [%4];"
        : "=r"(r[0]), "=r"(r[1]), "=r"(r[2]), "=r"(r[3]) : "r"(addr));
}
__device__ __forceinline__ void ldmx4t(uint32_t* r, uint32_t addr) {
    asm volatile("ldmatrix.sync.aligned.m8n8.x4.trans.shared.b16 {%0,%1,%2,%3}, [%4];"
        : "=r"(r[0]), "=r"(r[1]), "=r"(r[2]), "=r"(r[3]) : "r"(addr));
}
__device__ __forceinline__ void cp_async16(uint32_t d, const void* s) {
    asm volatile("cp.async.cg.shared.global [%0], [%1], 16;" :: "r"(d), "l"(s));
}
#define CP_COMMIT asm volatile("cp.async.commit_group;" ::: "memory")
#define CP_WAIT1  asm volatile("cp.async.wait_group 1;" ::: "memory")
#define CP_WAIT2  asm volatile("cp.async.wait_group 2;" ::: "memory")

// ---------------------------------------------------------------------------
// Batched fp32 -> fp16 converts (2 float4 per thread)
// ---------------------------------------------------------------------------
__global__ void conv_acts_kernel(const float* __restrict__ q, const float* __restrict__ k,
                                 const float* __restrict__ v, __half* __restrict__ out,
                                 int n4)
{
    const float* src = (blockIdx.y == 0) ? q : (blockIdx.y == 1) ? k : v;
    __half2* dst = (__half2*)(out + (size_t)blockIdx.y * MROWS * DMODEL);
    int i = blockIdx.x * 512 + threadIdx.x;
#pragma unroll
    for (int t = 0; t < 2; t++, i += 256) {
        if (i < n4) {
            float4 x = ((const float4*)src)[i];
            dst[i * 2 + 0] = __floats2half2_rn(x.x, x.y);
            dst[i * 2 + 1] = __floats2half2_rn(x.z, x.w);
        }
    }
}
__global__ void conv_ws_kernel(const float* __restrict__ w0, const float* __restrict__ w1,
                               const float* __restrict__ w2, const float* __restrict__ w3,
                               __half* __restrict__ out, int n4)
{
    const float* src = (blockIdx.y == 0) ? w0 : (blockIdx.y == 1) ? w1
                     : (blockIdx.y == 2) ? w2 : w3;
    __half2* dst = (__half2*)(out + (size_t)blockIdx.y * DMODEL * DMODEL);
    int i = blockIdx.x * 512 + threadIdx.x;
#pragma unroll
    for (int t = 0; t < 2; t++, i += 256) {
        if (i < n4) {
            float4 x = ((const float4*)src)[i];
            dst[i * 2 + 0] = __floats2half2_rn(x.x, x.y);
            dst[i * 2 + 1] = __floats2half2_rn(x.z, x.w);
        }
    }
}

// ---------------------------------------------------------------------------
// Pipelined HMMA GEMM (fp16 single pass, unchanged from R12)
// ---------------------------------------------------------------------------
#define LDT 40
#define TILE_B (128 * LDT * 2)
#define STAGE_B (2 * TILE_B)
#define GEMM_SMEM (2 * STAGE_B)

__global__ __launch_bounds__(256, 2)
void gemm_mma(const __half* __restrict__ A, const __half* __restrict__ W,
              const float* __restrict__ bias, float* __restrict__ C,
              __half* __restrict__ Chi, float alpha)
{
    extern __shared__ char smem[];
    const uint32_t sb = smem_u32(smem);

    const int tid = threadIdx.x;
    const int wid = tid >> 5;
    const int lane = tid & 31;
    const int wm = wid >> 2;
    const int wn = wid & 3;
    const int m0 = blockIdx.y * 128;
    const int n0 = blockIdx.x * 128;

    float acc[4][4][4];
#pragma unroll
    for (int i = 0; i < 4; i++)
#pragma unroll
        for (int j = 0; j < 4; j++)
#pragma unroll
            for (int k = 0; k < 4; k++) acc[i][j][k] = 0.f;

    const int lr = lane >> 2;
    const int lc = lane & 3;

    const int r0i = tid >> 2, c0i = tid & 3;
    const int r1i = (tid + 256) >> 2, c1i = tid & 3;

    const int aRow = wm * 64 + (lane & 15);
    const int aColB = ((lane >> 4) << 3) * 2;
    const int bRow = wn * 32 + ((lane >> 4) << 3) + (lane & 7);
    const int bColB = (((lane >> 3) & 1) << 3) * 2;

#define ISSUE(K0, ST) do {                                                     \
    uint32_t sd = sb + (ST) * STAGE_B;                                         \
    size_t g0 = (size_t)(m0 + r0i) * DMODEL + (K0) + c0i * 8;                  \
    size_t g1 = (size_t)(m0 + r1i) * DMODEL + (K0) + c1i * 8;                  \
    size_t h0 = (size_t)(n0 + r0i) * DMODEL + (K0) + c0i * 8;                  \
    size_t h1 = (size_t)(n0 + r1i) * DMODEL + (K0) + c1i * 8;                  \
    uint32_t d0 = r0i * (LDT * 2) + c0i * 16;                                  \
    uint32_t d1 = r1i * (LDT * 2) + c1i * 16;                                  \
    cp_async16(sd + 0 * TILE_B + d0, A + g0);                                  \
    cp_async16(sd + 0 * TILE_B + d1, A + g1);                                  \
    cp_async16(sd + 1 * TILE_B + d0, W + h0);                                  \
    cp_async16(sd + 1 * TILE_B + d1, W + h1);                                  \
} while (0)

    ISSUE(0, 0);
    CP_COMMIT;

    for (int it = 0; it < DMODEL / 32; it++) {
        if (it + 1 < DMODEL / 32) ISSUE((it + 1) * 32, (it + 1) & 1);
        CP_COMMIT;
        CP_WAIT1;
        __syncthreads();

        const uint32_t st = sb + (it & 1) * STAGE_B;
        const uint32_t aB = st + 0 * TILE_B;
        const uint32_t wB = st + 1 * TILE_B;

#pragma unroll
        for (int ks = 0; ks < 2; ks++) {
            const uint32_t acol = ks * 32 + aColB;
            const uint32_t bcol = ks * 32 + bColB;

            uint32_t bh[2][4];
#pragma unroll
            for (int nip = 0; nip < 2; nip++) {
                uint32_t boff = (uint32_t)(bRow + nip * 16) * (LDT * 2) + bcol;
                ldmx4(bh[nip], wB + boff);
            }
#pragma unroll
            for (int mi = 0; mi < 4; mi++) {
                uint32_t aoff = (uint32_t)(aRow + mi * 16) * (LDT * 2) + acol;
                uint32_t a[4];
                ldmx4(a, aB + aoff);
#pragma unroll
                for (int nip = 0; nip < 2; nip++) {
                    mma16816(acc[mi][2 * nip + 0], a, &bh[nip][0]);
                    mma16816(acc[mi][2 * nip + 1], a, &bh[nip][2]);
                }
            }
        }
        __syncthreads();
    }
#undef ISSUE

#pragma unroll
    for (int mi = 0; mi < 4; mi++) {
        int row = m0 + wm * 64 + mi * 16 + lr;
#pragma unroll
        for (int ni = 0; ni < 4; ni++) {
            int col = n0 + wn * 32 + ni * 8 + lc * 2;
            float2 b2 = *(const float2*)&bias[col];
            float v0x = alpha * (acc[mi][ni][0] + b2.x);
            float v0y = alpha * (acc[mi][ni][1] + b2.y);
            float v1x = alpha * (acc[mi][ni][2] + b2.x);
            float v1y = alpha * (acc[mi][ni][3] + b2.y);
            size_t p0 = (size_t)row * DMODEL + col;
            size_t p1 = (size_t)(row + 8) * DMODEL + col;
            if (C) {
                *(float2*)&C[p0] = make_float2(v0x, v0y);
                *(float2*)&C[p1] = make_float2(v1x, v1y);
            }
            if (Chi) {
                *(uint32_t*)&Chi[p0] = pack_h(v0x, v0y);
                *(uint32_t*)&Chi[p1] = pack_h(v1x, v1y);
            }
        }
    }
}

// ---------------------------------------------------------------------------
// Fused HMMA attention v6: QT=32, 512 threads, 1 CTA/SM, 4-stage cp.async
// ring (3-deep prefetch, one __syncthreads per tile), PV with no reduction.
// ---------------------------------------------------------------------------
#define QT 32
#define O_SC   0                          // 32 rows x 4096 B = 131072
#define O_QH   131072                     // 32*72*2 = 4608
#define O_KB   135680                     // 4 stages x 18432 = 73728
#define KSTG   18432
#define O_PEK  209408                     // 2304
#define O_PEV  211712                     // 2304
#define O_RB   214016                     // 1536
#define O_WS   215552                     // 1536
#define O_MSK  217088                     // 1024
#define ATT_SMEM 218112

__global__ __launch_bounds__(512, 1)
void attn_mma(const __half* __restrict__ qh,
              const __half* __restrict__ kh, const __half* __restrict__ vh,
              const int* __restrict__ mask, const float* __restrict__ pe_k,
              const float* __restrict__ pe_v, float* __restrict__ attn_out,
              __half* __restrict__ Oh)
{
    extern __shared__ char smem[];
    const uint32_t sb = smem_u32(smem);
    float* sc = (float*)smem;
    __half* QH = (__half*)(smem + O_QH);
    float* pek = (float*)(smem + O_PEK);
    float* pev = (float*)(smem + O_PEV);
    float* rb  = (float*)(smem + O_RB);
    float* ws  = (float*)(smem + O_WS);
    unsigned char* msk = (unsigned char*)(smem + O_MSK);

    const int b  = blockIdx.z;
    const int h  = blockIdx.y;
    const int qb = blockIdx.x * QT;
    const int tid = threadIdx.x;
    const int w = tid >> 5;
    const int lane = tid & 31;
    const int lr = lane >> 2;
    const int lc = lane & 3;

    const int liR0 = tid >> 3, liD0 = tid & 7;          // rows 0..63
    const int liR1 = (tid + 512) >> 3, liD1 = tid & 7;  // rows 64..127

    // K/V tile: 128 rows x 144 B (64 d + pad); each thread copies 2 x 16 B
#define ISSUE_T(SRC, TB, ST) do {                                              \
    uint32_t sd = sb + O_KB + (ST) * KSTG;                                     \
    size_t gA = (size_t)(b * S_LEN + (TB) * 128 + liR0) * DMODEL               \
              + h * DHEAD + liD0 * 8;                                          \
    size_t gB = (size_t)(b * S_LEN + (TB) * 128 + liR1) * DMODEL               \
              + h * DHEAD + liD1 * 8;                                          \
    cp_async16(sd + (uint32_t)(liR0 * 72 + liD0 * 8) * 2, (SRC) + gA);         \
    cp_async16(sd + (uint32_t)(liR1 * 72 + liD1 * 8) * 2, (SRC) + gB);         \
} while (0)

    // prologue: K0, K1, K2 into stages 0,1,2 (one group each)
    ISSUE_T(kh, 0, 0); CP_COMMIT;
    ISSUE_T(kh, 1, 1); CP_COMMIT;
    ISSUE_T(kh, 2, 2); CP_COMMIT;

    // load Q tile (32 rows x 8 chunks), pe tables, mask
    if (tid < 256) {
        int row = tid >> 3, dg = tid & 7;
        size_t g = (size_t)(b * S_LEN + qb + row) * DMODEL + h * DHEAD + dg * 8;
        *(uint4*)&QH[row * 72 + dg * 8] = *(const uint4*)&qh[g];
    }
    for (int i = tid; i < 576; i += 512) { pek[i] = pe_k[i]; pev[i] = pe_v[i]; }
    for (int i = tid; i < S_LEN; i += 512)
        msk[i] = (unsigned char)(mask[b * S_LEN + i] != 0);
    __syncthreads();

    for (int i = tid; i < QT * 9; i += 512) {
        int qi = i / 9, j = i % 9;
        float s = 0.f;
        const __half* qhr = QH + qi * 72;
        const float* pr = pek + j * 64;
#pragma unroll 16
        for (int d = 0; d < 64; d++)
            s += __half2float(qhr[d]) * pr[d];
        rb[qi * 12 + j] = s;
    }

    // hoist Q fragments (2 m-tiles)
    uint32_t qah[4][2][4];
#pragma unroll
    for (int ks = 0; ks < 4; ks++)
#pragma unroll
        for (int mt = 0; mt < 2; mt++) {
            int r = mt * 16 + lr;
            int kc = ks * 16 + lc * 2;
            qah[ks][mt][0] = *(const uint32_t*)&QH[r * 72 + kc];
            qah[ks][mt][1] = *(const uint32_t*)&QH[(r + 8) * 72 + kc];
            qah[ks][mt][2] = *(const uint32_t*)&QH[r * 72 + kc + 8];
            qah[ks][mt][3] = *(const uint32_t*)&QH[(r + 8) * 72 + kc + 8];
        }

    // ---- scores: 8 tiles of 128 k-cols; ring order: wait2,sync,ldmx,issue ----
    const int n0 = w * 8;
    for (int kb = 0; kb < 8; kb++) {
        CP_WAIT2;
        __syncthreads();

        const uint32_t kt = sb + O_KB + (kb & 3) * KSTG;
        uint32_t bh2[2][4];
#pragma unroll
        for (int j = 0; j < 2; j++) {
            uint32_t addr = kt + (uint32_t)(n0 + (lane & 7)) * 144
                          + j * 64 + (lane >> 3) * 16;
            ldmx4(bh2[j], addr);
        }

        {   // issue tile kb+3 (K, or V for tail) into stage (kb+3)&3
            int t = kb + 3;
            if (t < 8) { ISSUE_T(kh, t, t & 3); }
            else       { ISSUE_T(vh, t - 8, t & 3); }
            CP_COMMIT;
        }

        float c[2][4] = {{0.f,0.f,0.f,0.f},{0.f,0.f,0.f,0.f}};
#pragma unroll
        for (int ks = 0; ks < 4; ks++) {
            uint32_t* bh = &bh2[ks >> 1][(ks & 1) * 2];
#pragma unroll
            for (int mt = 0; mt < 2; mt++)
                mma16816(c[mt], qah[ks][mt], bh);
        }
#pragma unroll
        for (int mt = 0; mt < 2; mt++) {
#pragma unroll
            for (int half = 0; half < 2; half++) {
                int qi = mt * 16 + lr + half * 8;
                int qg = qb + qi;
                int kg = kb * 128 + n0 + lc * 2;
                float v0 = c[mt][half * 2 + 0];
                float v1 = c[mt][half * 2 + 1];
                int d0 = min(MAXK, max(-MAXK, kg - qg)) + MAXK;
                int d1 = min(MAXK, max(-MAXK, kg + 1 - qg)) + MAXK;
                v0 = msk[kg] ? v0 + rb[qi * 12 + d0] : -INFINITY;
                v1 = msk[kg + 1] ? v1 + rb[qi * 12 + d1] : -INFINITY;
                *(float2*)&sc[qi * S_LEN + kg] = make_float2(v0, v1);
            }
        }
    }
    __syncthreads();

    // ---- softmax: warp w -> rows 2w, 2w+1 (V0..V2 landing in background) ----
#pragma unroll
    for (int r = 0; r < 2; r++) {
        int qi = w * 2 + r;
        int qg = qb + qi;
        float* row = sc + qi * S_LEN;

        float m = -INFINITY;
        for (int k2 = lane; k2 < S_LEN; k2 += 32) m = fmaxf(m, row[k2]);
#pragma unroll
        for (int o = 16; o; o >>= 1) m = fmaxf(m, __shfl_xor_sync(0xFFFFFFFFu, m, o));

        float sum = 0.f;
        for (int k2 = lane; k2 < S_LEN; k2 += 32) {
            float e = __expf(row[k2] - m);
            row[k2] = e;
            sum += e;
        }
#pragma unroll
        for (int o = 16; o; o >>= 1) sum += __shfl_xor_sync(0xFFFFFFFFu, sum, o);
        float inv = 1.f / sum;

        float* ao = attn_out ? attn_out + ((size_t)(b * NHEAD + h) * S_LEN + qg) * S_LEN
                             : (float*)0;
        float w0 = 0.f, w8 = 0.f;
        for (int k2 = lane; k2 < S_LEN; k2 += 32) {
            float p = row[k2] * inv;
            row[k2] = p;
            if (ao) ao[k2] = p;
            if (k2 <= qg - MAXK) w0 += p;
            if (k2 >= qg + MAXK) w8 += p;
        }
#pragma unroll
        for (int o = 16; o; o >>= 1) {
            w0 += __shfl_xor_sync(0xFFFFFFFFu, w0, o);
            w8 += __shfl_xor_sync(0xFFFFFFFFu, w8, o);
        }
        __syncwarp();
        if (lane == 0) { ws[qi * 12 + 0] = w0; ws[qi * 12 + 8] = w8; }
        if (lane >= 1 && lane <= 7) {
            int k2 = qg + lane - MAXK;
            ws[qi * 12 + lane] = (k2 >= 0 && k2 < S_LEN) ? row[k2] : 0.f;
        }
        __syncwarp();

        // conflict-free in-place convert to fp16 (swizzled)
        float x[32];
#pragma unroll
        for (int t = 0; t < 16; t++) {
            float2 v = *(const float2*)(row + 2 * (lane + 32 * t));
            x[2 * t] = v.x;
            x[2 * t + 1] = v.y;
        }
        __syncwarp();
        uint32_t swz = (uint32_t)((qi & 7) << 4);
        char* rowb = smem + qi * 4096;
#pragma unroll
        for (int t = 0; t < 16; t++) {
            int j = lane + 32 * t;
            *(uint32_t*)(rowb + (((uint32_t)(4 * j)) ^ swz)) =
                pack_h(x[2 * t], x[2 * t + 1]);
        }
    }

    // ---- PV: warp (mw = w>>3, wn = w&7) owns m-tile mw, d-cols wn*8..+7 ----
    const int mw = w >> 3;
    const int wn = w & 7;
    float o[4] = {0.f, 0.f, 0.f, 0.f};
    const int prow = mw * 16 + (lane & 7) + ((lane >> 3) & 1) * 8;
    const uint32_t pswz = (uint32_t)((prow & 7) << 4);

    for (int vb = 0; vb < 8; vb++) {
        CP_WAIT2;
        __syncthreads();

        const uint32_t vtile = sb + O_KB + (vb & 3) * KSTG;
        uint32_t vbh[4][4];
#pragma unroll
        for (int j = 0; j < 4; j++) {
            uint32_t addr = vtile + (uint32_t)(j * 32 + lane) * 144 + wn * 16;
            ldmx4t(vbh[j], addr);
        }

        if (vb + 3 < 8) { ISSUE_T(vh, vb + 3, (vb + 3) & 3); }
        CP_COMMIT;   // empty group on tail keeps the count uniform

#pragma unroll
        for (int ks = 0; ks < 8; ks++) {
            uint32_t cby = (uint32_t)(vb * 256 + ks * 32 + (lane >> 4) * 16) ^ pswz;
            uint32_t a[4];
            ldmx4(a, sb + (uint32_t)prow * 4096 + cby);
            mma16816(o, a, &vbh[ks >> 1][(ks & 1) * 2]);
        }
    }

    // ---- epilogue: rel_v + write O (each warp owns its output) ----
#pragma unroll
    for (int half = 0; half < 2; half++) {
        int qi = mw * 16 + lr + half * 8;
        int d0 = wn * 8 + lc * 2;
        float a0 = o[half * 2 + 0];
        float a1 = o[half * 2 + 1];
#pragma unroll
        for (int j = 0; j < 9; j++) {
            float wv = ws[qi * 12 + j];
            a0 += wv * pev[j * 64 + d0];
            a1 += wv * pev[j * 64 + d0 + 1];
        }
        size_t base = (size_t)(b * S_LEN + qb + qi) * DMODEL + h * DHEAD + d0;
        *(uint32_t*)&Oh[base] = pack_h(a0, a1);
    }
}

// ---------------------------------------------------------------------------
extern "C" void kernel_launch(void* const* d_in, const int* in_sizes, int n_in,
                              void* d_out, int out_size)
{
    const float* query = (const float*)d_in[0];
    const float* key   = (const float*)d_in[1];
    const float* value = (const float*)d_in[2];
    const int*   mask  = (const int*)d_in[3];
    const float* Wq = (const float*)d_in[4];
    const float* bq = (const float*)d_in[5];
    const float* Wk = (const float*)d_in[6];
    const float* bk = (const float*)d_in[7];
    const float* Wv = (const float*)d_in[8];
    const float* bv = (const float*)d_in[9];
    const float* Wo = (const float*)d_in[10];
    const float* bo = (const float*)d_in[11];
    const float* pe_k = (const float*)d_in[12];
    const float* pe_v = (const float*)d_in[13];

    __half *act3, *w4, *qh, *kh, *vh, *oh;
    cudaGetSymbolAddress((void**)&act3, g_act3);
    cudaGetSymbolAddress((void**)&w4, g_w4);
    cudaGetSymbolAddress((void**)&qh, g_qh);
    cudaGetSymbolAddress((void**)&kh, g_kh);
    cudaGetSymbolAddress((void**)&vh, g_vh);
    cudaGetSymbolAddress((void**)&oh, g_oh);

    const long long OUT_ELEMS = (long long)BATCH * S_LEN * DMODEL;
    float* out_ptr  = (float*)d_out;
    float* attn_ptr = ((long long)out_size > OUT_ELEMS) ? (float*)d_out + OUT_ELEMS
                                                        : (float*)0;

    cudaFuncSetAttribute(attn_mma, cudaFuncAttributeMaxDynamicSharedMemorySize,
                         ATT_SMEM);
    cudaFuncSetAttribute(gemm_mma, cudaFuncAttributeMaxDynamicSharedMemorySize,
                         GEMM_SMEM);

    const int ACT4 = MROWS * DMODEL / 4;   // 2M float4 per tensor
    const int W4E  = DMODEL * DMODEL / 4;  // 256K float4 per weight
    const size_t WSTRIDE = (size_t)DMODEL * DMODEL;
    dim3 gg(DMODEL / 128, MROWS / 128);

    // batched converts: 3 activations, 4 weights
    conv_acts_kernel<<<dim3(ACT4 / 512, 3), 256>>>(query, key, value, act3, ACT4);
    conv_ws_kernel<<<dim3(W4E / 512, 4), 256>>>(Wq, Wk, Wv, Wo, w4, W4E);

    // projections (fold 1/SCALE into Q)
    gemm_mma<<<gg, 256, GEMM_SMEM>>>(act3 + 0 * (size_t)MROWS * DMODEL,
                                     w4 + 0 * WSTRIDE, bq, (float*)0, qh, 0.125f);
    gemm_mma<<<gg, 256, GEMM_SMEM>>>(act3 + 1 * (size_t)MROWS * DMODEL,
                                     w4 + 1 * WSTRIDE, bk, (float*)0, kh, 1.0f);
    gemm_mma<<<gg, 256, GEMM_SMEM>>>(act3 + 2 * (size_t)MROWS * DMODEL,
                                     w4 + 2 * WSTRIDE, bv, (float*)0, vh, 1.0f);

    // fused attention
    dim3 ga(S_LEN / QT, NHEAD, BATCH);   // (32, 16, 8)
    attn_mma<<<ga, 512, ATT_SMEM>>>(qh, kh, vh, mask, pe_k, pe_v, attn_ptr, oh);

    // output projection (fp32 out)
    gemm_mma<<<gg, 256, GEMM_SMEM>>>(oh, w4 + 3 * WSTRIDE, bo, out_ptr,
                                     (__half*)0, 1.0f);
}

// round 15
// speedup vs baseline: 1.0084x; 1.0084x over previous
#include <cuda_runtime.h>
#include <cuda_fp16.h>
#include <math.h>
#include <cstdint>

#define BATCH 8
#define S_LEN 1024
#define DMODEL 1024
#define NHEAD 16
#define DHEAD 64
#define MAXK 4
#define MROWS (BATCH * S_LEN)   // 8192

// Scratch (allocation-free rule -> device globals)
__device__ __half g_act3[(size_t)3 * MROWS * DMODEL];
__device__ __half g_w4[(size_t)4 * DMODEL * DMODEL];
__device__ __half g_qh[(size_t)MROWS * DMODEL];
__device__ __half g_kh[(size_t)MROWS * DMODEL];
__device__ __half g_vh[(size_t)MROWS * DMODEL];
__device__ __half g_oh[(size_t)MROWS * DMODEL];

// ---------------------------------------------------------------------------
__device__ __forceinline__ void mma16816(float* c, const uint32_t* a, const uint32_t* b) {
    asm volatile(
        "mma.sync.aligned.m16n8k16.row.col.f32.f16.f16.f32 "
        "{%0,%1,%2,%3}, {%4,%5,%6,%7}, {%8,%9}, {%0,%1,%2,%3};"
        : "+f"(c[0]), "+f"(c[1]), "+f"(c[2]), "+f"(c[3])
        : "r"(a[0]), "r"(a[1]), "r"(a[2]), "r"(a[3]), "r"(b[0]), "r"(b[1]));
}
__device__ __forceinline__ uint32_t pack_h(float x, float y) {
    __half2 t = __floats2half2_rn(x, y);
    return *(uint32_t*)&t;
}
__device__ __forceinline__ uint32_t smem_u32(const void* p) {
    uint32_t a;
    asm("{ .reg .u64 t; cvta.to.shared.u64 t, %1; cvt.u32.u64 %0, t; }"
        : "=r"(a) : "l"(p));
    return a;
}
__device__ __forceinline__ void ldmx4(uint32_t* r, uint32_t addr) {
    asm volatile("ldmatrix.sync.aligned.m8n8.x4.shared.b16 {%0,%1,%2,%3}, [%4];"
        : "=r"(r[0]), "=r"(r[1]), "=r"(r[2]), "=r"(r[3]) : "r"(addr));
}
__device__ __forceinline__ void ldmx4t(uint32_t* r, uint32_t addr) {
    asm volatile("ldmatrix.sync.aligned.m8n8.x4.trans.shared.b16 {%0,%1,%2,%3}, [%4];"
        : "=r"(r[0]), "=r"(r[1]), "=r"(r[2]), "=r"(r[3]) : "r"(addr));
}
__device__ __forceinline__ void cp_async16(uint32_t d, const void* s) {
    asm volatile("cp.async.cg.shared.global [%0], [%1], 16;" :: "r"(d), "l"(s));
}
#define CP_COMMIT asm volatile("cp.async.commit_group;" ::: "memory")
#define CP_WAIT2  asm volatile("cp.async.wait_group 2;" ::: "memory")

// ---------------------------------------------------------------------------
// Batched fp32 -> fp16 converts (2 float4 per thread)
// ---------------------------------------------------------------------------
__global__ void conv_acts_kernel(const float* __restrict__ q, const float* __restrict__ k,
                                 const float* __restrict__ v, __half* __restrict__ out,
                                 int n4)
{
    const float* src = (blockIdx.y == 0) ? q : (blockIdx.y == 1) ? k : v;
    __half2* dst = (__half2*)(out + (size_t)blockIdx.y * MROWS * DMODEL);
    int i = blockIdx.x * 512 + threadIdx.x;
#pragma unroll
    for (int t = 0; t < 2; t++, i += 256) {
        if (i < n4) {
            float4 x = ((const float4*)src)[i];
            dst[i * 2 + 0] = __floats2half2_rn(x.x, x.y);
            dst[i * 2 + 1] = __floats2half2_rn(x.z, x.w);
        }
    }
}
__global__ void conv_ws_kernel(const float* __restrict__ w0, const float* __restrict__ w1,
                               const float* __restrict__ w2, const float* __restrict__ w3,
                               __half* __restrict__ out, int n4)
{
    const float* src = (blockIdx.y == 0) ? w0 : (blockIdx.y == 1) ? w1
                     : (blockIdx.y == 2) ? w2 : w3;
    __half2* dst = (__half2*)(out + (size_t)blockIdx.y * DMODEL * DMODEL);
    int i = blockIdx.x * 512 + threadIdx.x;
#pragma unroll
    for (int t = 0; t < 2; t++, i += 256) {
        if (i < n4) {
            float4 x = ((const float4*)src)[i];
            dst[i * 2 + 0] = __floats2half2_rn(x.x, x.y);
            dst[i * 2 + 1] = __floats2half2_rn(x.z, x.w);
        }
    }
}

// ---------------------------------------------------------------------------
// Pipelined HMMA GEMM v3 (fp16 single pass, 4-stage cp.async ring,
// single __syncthreads per k-iteration): C = alpha*(A @ W^T + bias)
// ---------------------------------------------------------------------------
#define LDT 40
#define TILE_B (128 * LDT * 2)      // 10240
#define STAGE_B (2 * TILE_B)        // 20480 (A, W)
#define GEMM_SMEM (4 * STAGE_B)     // 81920

__global__ __launch_bounds__(256, 2)
void gemm_mma(const __half* __restrict__ A, const __half* __restrict__ W,
              const float* __restrict__ bias, float* __restrict__ C,
              __half* __restrict__ Chi, float alpha)
{
    extern __shared__ char smem[];
    const uint32_t sb = smem_u32(smem);

    const int tid = threadIdx.x;
    const int wid = tid >> 5;
    const int lane = tid & 31;
    const int wm = wid >> 2;
    const int wn = wid & 3;
    const int m0 = blockIdx.y * 128;
    const int n0 = blockIdx.x * 128;

    float acc[4][4][4];
#pragma unroll
    for (int i = 0; i < 4; i++)
#pragma unroll
        for (int j = 0; j < 4; j++)
#pragma unroll
            for (int k = 0; k < 4; k++) acc[i][j][k] = 0.f;

    const int lr = lane >> 2;
    const int lc = lane & 3;

    const int r0i = tid >> 2, c0i = tid & 3;
    const int r1i = (tid + 256) >> 2, c1i = tid & 3;

    const int aRow = wm * 64 + (lane & 15);
    const int aColB = ((lane >> 4) << 3) * 2;
    const int bRow = wn * 32 + ((lane >> 4) << 3) + (lane & 7);
    const int bColB = (((lane >> 3) & 1) << 3) * 2;

#define ISSUE(K0, ST) do {                                                     \
    uint32_t sd = sb + (ST) * STAGE_B;                                         \
    size_t g0 = (size_t)(m0 + r0i) * DMODEL + (K0) + c0i * 8;                  \
    size_t g1 = (size_t)(m0 + r1i) * DMODEL + (K0) + c1i * 8;                  \
    size_t h0 = (size_t)(n0 + r0i) * DMODEL + (K0) + c0i * 8;                  \
    size_t h1 = (size_t)(n0 + r1i) * DMODEL + (K0) + c1i * 8;                  \
    uint32_t d0 = r0i * (LDT * 2) + c0i * 16;                                  \
    uint32_t d1 = r1i * (LDT * 2) + c1i * 16;                                  \
    cp_async16(sd + 0 * TILE_B + d0, A + g0);                                  \
    cp_async16(sd + 0 * TILE_B + d1, A + g1);                                  \
    cp_async16(sd + 1 * TILE_B + d0, W + h0);                                  \
    cp_async16(sd + 1 * TILE_B + d1, W + h1);                                  \
} while (0)

    // prologue: stages 0,1,2 in flight
    ISSUE(0, 0);  CP_COMMIT;
    ISSUE(32, 1); CP_COMMIT;
    ISSUE(64, 2); CP_COMMIT;

    for (int it = 0; it < DMODEL / 32; it++) {
        CP_WAIT2;            // oldest stage (it&3) complete
        __syncthreads();     // publish; also orders last iter's reads

        {   // issue stage (it+3)&3 (empty commit on tail keeps counts uniform)
            int nt = it + 3;
            if (nt < DMODEL / 32) ISSUE(nt * 32, nt & 3);
            CP_COMMIT;
        }

        const uint32_t st = sb + (it & 3) * STAGE_B;
        const uint32_t aB = st + 0 * TILE_B;
        const uint32_t wB = st + 1 * TILE_B;

#pragma unroll
        for (int ks = 0; ks < 2; ks++) {
            const uint32_t acol = ks * 32 + aColB;
            const uint32_t bcol = ks * 32 + bColB;

            uint32_t bh[2][4];
#pragma unroll
            for (int nip = 0; nip < 2; nip++) {
                uint32_t boff = (uint32_t)(bRow + nip * 16) * (LDT * 2) + bcol;
                ldmx4(bh[nip], wB + boff);
            }
#pragma unroll
            for (int mi = 0; mi < 4; mi++) {
                uint32_t aoff = (uint32_t)(aRow + mi * 16) * (LDT * 2) + acol;
                uint32_t a[4];
                ldmx4(a, aB + aoff);
#pragma unroll
                for (int nip = 0; nip < 2; nip++) {
                    mma16816(acc[mi][2 * nip + 0], a, &bh[nip][0]);
                    mma16816(acc[mi][2 * nip + 1], a, &bh[nip][2]);
                }
            }
        }
    }
#undef ISSUE

#pragma unroll
    for (int mi = 0; mi < 4; mi++) {
        int row = m0 + wm * 64 + mi * 16 + lr;
#pragma unroll
        for (int ni = 0; ni < 4; ni++) {
            int col = n0 + wn * 32 + ni * 8 + lc * 2;
            float2 b2 = *(const float2*)&bias[col];
            float v0x = alpha * (acc[mi][ni][0] + b2.x);
            float v0y = alpha * (acc[mi][ni][1] + b2.y);
            float v1x = alpha * (acc[mi][ni][2] + b2.x);
            float v1y = alpha * (acc[mi][ni][3] + b2.y);
            size_t p0 = (size_t)row * DMODEL + col;
            size_t p1 = (size_t)(row + 8) * DMODEL + col;
            if (C) {
                *(float2*)&C[p0] = make_float2(v0x, v0y);
                *(float2*)&C[p1] = make_float2(v1x, v1y);
            }
            if (Chi) {
                *(uint32_t*)&Chi[p0] = pack_h(v0x, v0y);
                *(uint32_t*)&Chi[p1] = pack_h(v1x, v1y);
            }
        }
    }
}

// ---------------------------------------------------------------------------
// Fused HMMA attention v6 (unchanged from R14): QT=32, 512 threads,
// 4-stage cp.async ring, PV with no reduction.
// ---------------------------------------------------------------------------
#define QT 32
#define O_SC   0
#define O_QH   131072
#define O_KB   135680
#define KSTG   18432
#define O_PEK  209408
#define O_PEV  211712
#define O_RB   214016
#define O_WS   215552
#define O_MSK  217088
#define ATT_SMEM 218112

__global__ __launch_bounds__(512, 1)
void attn_mma(const __half* __restrict__ qh,
              const __half* __restrict__ kh, const __half* __restrict__ vh,
              const int* __restrict__ mask, const float* __restrict__ pe_k,
              const float* __restrict__ pe_v, float* __restrict__ attn_out,
              __half* __restrict__ Oh)
{
    extern __shared__ char smem[];
    const uint32_t sb = smem_u32(smem);
    float* sc = (float*)smem;
    __half* QH = (__half*)(smem + O_QH);
    float* pek = (float*)(smem + O_PEK);
    float* pev = (float*)(smem + O_PEV);
    float* rb  = (float*)(smem + O_RB);
    float* ws  = (float*)(smem + O_WS);
    unsigned char* msk = (unsigned char*)(smem + O_MSK);

    const int b  = blockIdx.z;
    const int h  = blockIdx.y;
    const int qb = blockIdx.x * QT;
    const int tid = threadIdx.x;
    const int w = tid >> 5;
    const int lane = tid & 31;
    const int lr = lane >> 2;
    const int lc = lane & 3;

    const int liR0 = tid >> 3, liD0 = tid & 7;
    const int liR1 = (tid + 512) >> 3, liD1 = tid & 7;

#define ISSUE_T(SRC, TB, ST) do {                                              \
    uint32_t sd = sb + O_KB + (ST) * KSTG;                                     \
    size_t gA = (size_t)(b * S_LEN + (TB) * 128 + liR0) * DMODEL               \
              + h * DHEAD + liD0 * 8;                                          \
    size_t gB = (size_t)(b * S_LEN + (TB) * 128 + liR1) * DMODEL               \
              + h * DHEAD + liD1 * 8;                                          \
    cp_async16(sd + (uint32_t)(liR0 * 72 + liD0 * 8) * 2, (SRC) + gA);         \
    cp_async16(sd + (uint32_t)(liR1 * 72 + liD1 * 8) * 2, (SRC) + gB);         \
} while (0)

    ISSUE_T(kh, 0, 0); CP_COMMIT;
    ISSUE_T(kh, 1, 1); CP_COMMIT;
    ISSUE_T(kh, 2, 2); CP_COMMIT;

    if (tid < 256) {
        int row = tid >> 3, dg = tid & 7;
        size_t g = (size_t)(b * S_LEN + qb + row) * DMODEL + h * DHEAD + dg * 8;
        *(uint4*)&QH[row * 72 + dg * 8] = *(const uint4*)&qh[g];
    }
    for (int i = tid; i < 576; i += 512) { pek[i] = pe_k[i]; pev[i] = pe_v[i]; }
    for (int i = tid; i < S_LEN; i += 512)
        msk[i] = (unsigned char)(mask[b * S_LEN + i] != 0);
    __syncthreads();

    for (int i = tid; i < QT * 9; i += 512) {
        int qi = i / 9, j = i % 9;
        float s = 0.f;
        const __half* qhr = QH + qi * 72;
        const float* pr = pek + j * 64;
#pragma unroll 16
        for (int d = 0; d < 64; d++)
            s += __half2float(qhr[d]) * pr[d];
        rb[qi * 12 + j] = s;
    }

    uint32_t qah[4][2][4];
#pragma unroll
    for (int ks = 0; ks < 4; ks++)
#pragma unroll
        for (int mt = 0; mt < 2; mt++) {
            int r = mt * 16 + lr;
            int kc = ks * 16 + lc * 2;
            qah[ks][mt][0] = *(const uint32_t*)&QH[r * 72 + kc];
            qah[ks][mt][1] = *(const uint32_t*)&QH[(r + 8) * 72 + kc];
            qah[ks][mt][2] = *(const uint32_t*)&QH[r * 72 + kc + 8];
            qah[ks][mt][3] = *(const uint32_t*)&QH[(r + 8) * 72 + kc + 8];
        }

    // ---- scores: 8 tiles of 128 k-cols; ring ----
    const int n0 = w * 8;
    for (int kb = 0; kb < 8; kb++) {
        CP_WAIT2;
        __syncthreads();

        const uint32_t kt = sb + O_KB + (kb & 3) * KSTG;
        uint32_t bh2[2][4];
#pragma unroll
        for (int j = 0; j < 2; j++) {
            uint32_t addr = kt + (uint32_t)(n0 + (lane & 7)) * 144
                          + j * 64 + (lane >> 3) * 16;
            ldmx4(bh2[j], addr);
        }

        {
            int t = kb + 3;
            if (t < 8) { ISSUE_T(kh, t, t & 3); }
            else       { ISSUE_T(vh, t - 8, t & 3); }
            CP_COMMIT;
        }

        float c[2][4] = {{0.f,0.f,0.f,0.f},{0.f,0.f,0.f,0.f}};
#pragma unroll
        for (int ks = 0; ks < 4; ks++) {
            uint32_t* bh = &bh2[ks >> 1][(ks & 1) * 2];
#pragma unroll
            for (int mt = 0; mt < 2; mt++)
                mma16816(c[mt], qah[ks][mt], bh);
        }
#pragma unroll
        for (int mt = 0; mt < 2; mt++) {
#pragma unroll
            for (int half = 0; half < 2; half++) {
                int qi = mt * 16 + lr + half * 8;
                int qg = qb + qi;
                int kg = kb * 128 + n0 + lc * 2;
                float v0 = c[mt][half * 2 + 0];
                float v1 = c[mt][half * 2 + 1];
                int d0 = min(MAXK, max(-MAXK, kg - qg)) + MAXK;
                int d1 = min(MAXK, max(-MAXK, kg + 1 - qg)) + MAXK;
                v0 = msk[kg] ? v0 + rb[qi * 12 + d0] : -INFINITY;
                v1 = msk[kg + 1] ? v1 + rb[qi * 12 + d1] : -INFINITY;
                *(float2*)&sc[qi * S_LEN + kg] = make_float2(v0, v1);
            }
        }
    }
    __syncthreads();

    // ---- softmax: warp w -> rows 2w, 2w+1 ----
#pragma unroll
    for (int r = 0; r < 2; r++) {
        int qi = w * 2 + r;
        int qg = qb + qi;
        float* row = sc + qi * S_LEN;

        float m = -INFINITY;
        for (int k2 = lane; k2 < S_LEN; k2 += 32) m = fmaxf(m, row[k2]);
#pragma unroll
        for (int o = 16; o; o >>= 1) m = fmaxf(m, __shfl_xor_sync(0xFFFFFFFFu, m, o));

        float sum = 0.f;
        for (int k2 = lane; k2 < S_LEN; k2 += 32) {
            float e = __expf(row[k2] - m);
            row[k2] = e;
            sum += e;
        }
#pragma unroll
        for (int o = 16; o; o >>= 1) sum += __shfl_xor_sync(0xFFFFFFFFu, sum, o);
        float inv = 1.f / sum;

        float* ao = attn_out ? attn_out + ((size_t)(b * NHEAD + h) * S_LEN + qg) * S_LEN
                             : (float*)0;
        float w0 = 0.f, w8 = 0.f;
        for (int k2 = lane; k2 < S_LEN; k2 += 32) {
            float p = row[k2] * inv;
            row[k2] = p;
            if (ao) ao[k2] = p;
            if (k2 <= qg - MAXK) w0 += p;
            if (k2 >= qg + MAXK) w8 += p;
        }
#pragma unroll
        for (int o = 16; o; o >>= 1) {
            w0 += __shfl_xor_sync(0xFFFFFFFFu, w0, o);
            w8 += __shfl_xor_sync(0xFFFFFFFFu, w8, o);
        }
        __syncwarp();
        if (lane == 0) { ws[qi * 12 + 0] = w0; ws[qi * 12 + 8] = w8; }
        if (lane >= 1 && lane <= 7) {
            int k2 = qg + lane - MAXK;
            ws[qi * 12 + lane] = (k2 >= 0 && k2 < S_LEN) ? row[k2] : 0.f;
        }
        __syncwarp();

        float x[32];
#pragma unroll
        for (int t = 0; t < 16; t++) {
            float2 v = *(const float2*)(row + 2 * (lane + 32 * t));
            x[2 * t] = v.x;
            x[2 * t + 1] = v.y;
        }
        __syncwarp();
        uint32_t swz = (uint32_t)((qi & 7) << 4);
        char* rowb = smem + qi * 4096;
#pragma unroll
        for (int t = 0; t < 16; t++) {
            int j = lane + 32 * t;
            *(uint32_t*)(rowb + (((uint32_t)(4 * j)) ^ swz)) =
                pack_h(x[2 * t], x[2 * t + 1]);
        }
    }

    // ---- PV: warp (mw, wn) owns m-tile mw, d-cols wn*8..+7 ----
    const int mw = w >> 3;
    const int wn = w & 7;
    float o[4] = {0.f, 0.f, 0.f, 0.f};
    const int prow = mw * 16 + (lane & 7) + ((lane >> 3) & 1) * 8;
    const uint32_t pswz = (uint32_t)((prow & 7) << 4);

    for (int vb = 0; vb < 8; vb++) {
        CP_WAIT2;
        __syncthreads();

        const uint32_t vtile = sb + O_KB + (vb & 3) * KSTG;
        uint32_t vbh[4][4];
#pragma unroll
        for (int j = 0; j < 4; j++) {
            uint32_t addr = vtile + (uint32_t)(j * 32 + lane) * 144 + wn * 16;
            ldmx4t(vbh[j], addr);
        }

        if (vb + 3 < 8) { ISSUE_T(vh, vb + 3, (vb + 3) & 3); }
        CP_COMMIT;

#pragma unroll
        for (int ks = 0; ks < 8; ks++) {
            uint32_t cby = (uint32_t)(vb * 256 + ks * 32 + (lane >> 4) * 16) ^ pswz;
            uint32_t a[4];
            ldmx4(a, sb + (uint32_t)prow * 4096 + cby);
            mma16816(o, a, &vbh[ks >> 1][(ks & 1) * 2]);
        }
    }

    // ---- epilogue: rel_v + write O ----
#pragma unroll
    for (int half = 0; half < 2; half++) {
        int qi = mw * 16 + lr + half * 8;
        int d0 = wn * 8 + lc * 2;
        float a0 = o[half * 2 + 0];
        float a1 = o[half * 2 + 1];
#pragma unroll
        for (int j = 0; j < 9; j++) {
            float wv = ws[qi * 12 + j];
            a0 += wv * pev[j * 64 + d0];
            a1 += wv * pev[j * 64 + d0 + 1];
        }
        size_t base = (size_t)(b * S_LEN + qb + qi) * DMODEL + h * DHEAD + d0;
        *(uint32_t*)&Oh[base] = pack_h(a0, a1);
    }
}

// ---------------------------------------------------------------------------
extern "C" void kernel_launch(void* const* d_in, const int* in_sizes, int n_in,
                              void* d_out, int out_size)
{
    const float* query = (const float*)d_in[0];
    const float* key   = (const float*)d_in[1];
    const float* value = (const float*)d_in[2];
    const int*   mask  = (const int*)d_in[3];
    const float* Wq = (const float*)d_in[4];
    const float* bq = (const float*)d_in[5];
    const float* Wk = (const float*)d_in[6];
    const float* bk = (const float*)d_in[7];
    const float* Wv = (const float*)d_in[8];
    const float* bv = (const float*)d_in[9];
    const float* Wo = (const float*)d_in[10];
    const float* bo = (const float*)d_in[11];
    const float* pe_k = (const float*)d_in[12];
    const float* pe_v = (const float*)d_in[13];

    __half *act3, *w4, *qh, *kh, *vh, *oh;
    cudaGetSymbolAddress((void**)&act3, g_act3);
    cudaGetSymbolAddress((void**)&w4, g_w4);
    cudaGetSymbolAddress((void**)&qh, g_qh);
    cudaGetSymbolAddress((void**)&kh, g_kh);
    cudaGetSymbolAddress((void**)&vh, g_vh);
    cudaGetSymbolAddress((void**)&oh, g_oh);

    const long long OUT_ELEMS = (long long)BATCH * S_LEN * DMODEL;
    float* out_ptr  = (float*)d_out;
    float* attn_ptr = ((long long)out_size > OUT_ELEMS) ? (float*)d_out + OUT_ELEMS
                                                        : (float*)0;

    cudaFuncSetAttribute(attn_mma, cudaFuncAttributeMaxDynamicSharedMemorySize,
                         ATT_SMEM);
    cudaFuncSetAttribute(gemm_mma, cudaFuncAttributeMaxDynamicSharedMemorySize,
                         GEMM_SMEM);

    const int ACT4 = MROWS * DMODEL / 4;
    const int W4E  = DMODEL * DMODEL / 4;
    const size_t WSTRIDE = (size_t)DMODEL * DMODEL;
    dim3 gg(DMODEL / 128, MROWS / 128);

    conv_acts_kernel<<<dim3(ACT4 / 512, 3), 256>>>(query, key, value, act3, ACT4);
    conv_ws_kernel<<<dim3(W4E / 512, 4), 256>>>(Wq, Wk, Wv, Wo, w4, W4E);

    gemm_mma<<<gg, 256, GEMM_SMEM>>>(act3 + 0 * (size_t)MROWS * DMODEL,
                                     w4 + 0 * WSTRIDE, bq, (float*)0, qh, 0.125f);
    gemm_mma<<<gg, 256, GEMM_SMEM>>>(act3 + 1 * (size_t)MROWS * DMODEL,
                                     w4 + 1 * WSTRIDE, bk, (float*)0, kh, 1.0f);
    gemm_mma<<<gg, 256, GEMM_SMEM>>>(act3 + 2 * (size_t)MROWS * DMODEL,
                                     w4 + 2 * WSTRIDE, bv, (float*)0, vh, 1.0f);

    dim3 ga(S_LEN / QT, NHEAD, BATCH);   // (32, 16, 8)
    attn_mma<<<ga, 512, ATT_SMEM>>>(qh, kh, vh, mask, pe_k, pe_v, attn_ptr, oh);

    gemm_mma<<<gg, 256, GEMM_SMEM>>>(oh, w4 + 3 * WSTRIDE, bo, out_ptr,
                                     (__half*)0, 1.0f);
}

// round 16
// speedup vs baseline: 1.0523x; 1.0436x over previous
#include <cuda_runtime.h>
#include <cuda_fp16.h>
#include <math.h>
#include <cstdint>

#define BATCH 8
#define S_LEN 1024
#define DMODEL 1024
#define NHEAD 16
#define DHEAD 64
#define MAXK 4
#define MROWS (BATCH * S_LEN)   // 8192

// Scratch (allocation-free rule -> device globals)
__device__ __half g_act3[(size_t)3 * MROWS * DMODEL];
__device__ __half g_w4[(size_t)4 * DMODEL * DMODEL];
__device__ __half g_qh[(size_t)MROWS * DMODEL];
__device__ __half g_kh[(size_t)MROWS * DMODEL];
__device__ __half g_vh[(size_t)MROWS * DMODEL];
__device__ __half g_oh[(size_t)MROWS * DMODEL];

// ---------------------------------------------------------------------------
__device__ __forceinline__ void mma16816(float* c, const uint32_t* a, const uint32_t* b) {
    asm volatile(
        "mma.sync.aligned.m16n8k16.row.col.f32.f16.f16.f32 "
        "{%0,%1,%2,%3}, {%4,%5,%6,%7}, {%8,%9}, {%0,%1,%2,%3};"
        : "+f"(c[0]), "+f"(c[1]), "+f"(c[2]), "+f"(c[3])
        : "r"(a[0]), "r"(a[1]), "r"(a[2]), "r"(a[3]), "r"(b[0]), "r"(b[1]));
}
__device__ __forceinline__ uint32_t pack_h(float x, float y) {
    __half2 t = __floats2half2_rn(x, y);
    return *(uint32_t*)&t;
}
__device__ __forceinline__ uint32_t smem_u32(const void* p) {
    uint32_t a;
    asm("{ .reg .u64 t; cvta.to.shared.u64 t, %1; cvt.u32.u64 %0, t; }"
        : "=r"(a) : "l"(p));
    return a;
}
__device__ __forceinline__ void ldmx4(uint32_t* r, uint32_t addr) {
    asm volatile("ldmatrix.sync.aligned.m8n8.x4.shared.b16 {%0,%1,%2,%3}, [%4];"
        : "=r"(r[0]), "=r"(r[1]), "=r"(r[2]), "=r"(r[3]) : "r"(addr));
}
__device__ __forceinline__ void ldmx4t(uint32_t* r, uint32_t addr) {
    asm volatile("ldmatrix.sync.aligned.m8n8.x4.trans.shared.b16 {%0,%1,%2,%3}, [%4];"
        : "=r"(r[0]), "=r"(r[1]), "=r"(r[2]), "=r"(r[3]) : "r"(addr));
}
__device__ __forceinline__ void cp_async16(uint32_t d, const void* s) {
    asm volatile("cp.async.cg.shared.global [%0], [%1], 16;" :: "r"(d), "l"(s));
}
#define CP_COMMIT asm volatile("cp.async.commit_group;" ::: "memory")
#define CP_WAIT2  asm volatile("cp.async.wait_group 2;" ::: "memory")

// ---------------------------------------------------------------------------
// Unified fp32 -> fp16 convert: flat index over 3 activations + 4 weights
// ---------------------------------------------------------------------------
#define ACT4C (MROWS * DMODEL / 4)      // 2097152 float4 per activation
#define W4C   (DMODEL * DMODEL / 4)     // 262144 float4 per weight
#define TOT4  (3 * ACT4C + 4 * W4C)     // 7340032

__global__ void conv_all_kernel(const float* __restrict__ q, const float* __restrict__ k,
                                const float* __restrict__ v,
                                const float* __restrict__ w0, const float* __restrict__ w1,
                                const float* __restrict__ w2, const float* __restrict__ w3,
                                __half* __restrict__ act3, __half* __restrict__ w4)
{
    int i = blockIdx.x * 512 + threadIdx.x;
#pragma unroll
    for (int t = 0; t < 2; t++, i += 256) {
        if (i >= TOT4) return;
        const float* src;
        __half2* dst;
        int off;
        if (i < 3 * ACT4C) {
            int ti = i / ACT4C;
            off = i - ti * ACT4C;
            src = (ti == 0) ? q : (ti == 1) ? k : v;
            dst = (__half2*)(act3 + (size_t)ti * MROWS * DMODEL);
        } else {
            int j = i - 3 * ACT4C;
            int ti = j / W4C;
            off = j - ti * W4C;
            src = (ti == 0) ? w0 : (ti == 1) ? w1 : (ti == 2) ? w2 : w3;
            dst = (__half2*)(w4 + (size_t)ti * DMODEL * DMODEL);
        }
        float4 x = ((const float4*)src)[off];
        dst[off * 2 + 0] = __floats2half2_rn(x.x, x.y);
        dst[off * 2 + 1] = __floats2half2_rn(x.z, x.w);
    }
}

// ---------------------------------------------------------------------------
// Pipelined HMMA GEMM body (fp16 single pass, 4-stage cp.async ring)
// ---------------------------------------------------------------------------
#define LDT 40
#define TILE_B (128 * LDT * 2)      // 10240
#define STAGE_B (2 * TILE_B)        // 20480 (A, W)
#define GEMM_SMEM (4 * STAGE_B)     // 81920

__device__ __forceinline__
void gemm_body(const __half* __restrict__ A, const __half* __restrict__ W,
               const float* __restrict__ bias, float* __restrict__ C,
               __half* __restrict__ Chi, float alpha, char* smem)
{
    const uint32_t sb = smem_u32(smem);

    const int tid = threadIdx.x;
    const int wid = tid >> 5;
    const int lane = tid & 31;
    const int wm = wid >> 2;
    const int wn = wid & 3;
    const int m0 = blockIdx.y * 128;
    const int n0 = blockIdx.x * 128;

    float acc[4][4][4];
#pragma unroll
    for (int i = 0; i < 4; i++)
#pragma unroll
        for (int j = 0; j < 4; j++)
#pragma unroll
            for (int k = 0; k < 4; k++) acc[i][j][k] = 0.f;

    const int lr = lane >> 2;
    const int lc = lane & 3;

    const int r0i = tid >> 2, c0i = tid & 3;
    const int r1i = (tid + 256) >> 2, c1i = tid & 3;

    const int aRow = wm * 64 + (lane & 15);
    const int aColB = ((lane >> 4) << 3) * 2;
    const int bRow = wn * 32 + ((lane >> 4) << 3) + (lane & 7);
    const int bColB = (((lane >> 3) & 1) << 3) * 2;

#define ISSUE(K0, ST) do {                                                     \
    uint32_t sd = sb + (ST) * STAGE_B;                                         \
    size_t g0 = (size_t)(m0 + r0i) * DMODEL + (K0) + c0i * 8;                  \
    size_t g1 = (size_t)(m0 + r1i) * DMODEL + (K0) + c1i * 8;                  \
    size_t h0 = (size_t)(n0 + r0i) * DMODEL + (K0) + c0i * 8;                  \
    size_t h1 = (size_t)(n0 + r1i) * DMODEL + (K0) + c1i * 8;                  \
    uint32_t d0 = r0i * (LDT * 2) + c0i * 16;                                  \
    uint32_t d1 = r1i * (LDT * 2) + c1i * 16;                                  \
    cp_async16(sd + 0 * TILE_B + d0, A + g0);                                  \
    cp_async16(sd + 0 * TILE_B + d1, A + g1);                                  \
    cp_async16(sd + 1 * TILE_B + d0, W + h0);                                  \
    cp_async16(sd + 1 * TILE_B + d1, W + h1);                                  \
} while (0)

    ISSUE(0, 0);  CP_COMMIT;
    ISSUE(32, 1); CP_COMMIT;
    ISSUE(64, 2); CP_COMMIT;

    for (int it = 0; it < DMODEL / 32; it++) {
        CP_WAIT2;
        __syncthreads();

        {
            int nt = it + 3;
            if (nt < DMODEL / 32) ISSUE(nt * 32, nt & 3);
            CP_COMMIT;
        }

        const uint32_t st = sb + (it & 3) * STAGE_B;
        const uint32_t aB = st + 0 * TILE_B;
        const uint32_t wB = st + 1 * TILE_B;

#pragma unroll
        for (int ks = 0; ks < 2; ks++) {
            const uint32_t acol = ks * 32 + aColB;
            const uint32_t bcol = ks * 32 + bColB;

            uint32_t bh[2][4];
#pragma unroll
            for (int nip = 0; nip < 2; nip++) {
                uint32_t boff = (uint32_t)(bRow + nip * 16) * (LDT * 2) + bcol;
                ldmx4(bh[nip], wB + boff);
            }
#pragma unroll
            for (int mi = 0; mi < 4; mi++) {
                uint32_t aoff = (uint32_t)(aRow + mi * 16) * (LDT * 2) + acol;
                uint32_t a[4];
                ldmx4(a, aB + aoff);
#pragma unroll
                for (int nip = 0; nip < 2; nip++) {
                    mma16816(acc[mi][2 * nip + 0], a, &bh[nip][0]);
                    mma16816(acc[mi][2 * nip + 1], a, &bh[nip][2]);
                }
            }
        }
    }
#undef ISSUE

#pragma unroll
    for (int mi = 0; mi < 4; mi++) {
        int row = m0 + wm * 64 + mi * 16 + lr;
#pragma unroll
        for (int ni = 0; ni < 4; ni++) {
            int col = n0 + wn * 32 + ni * 8 + lc * 2;
            float2 b2 = *(const float2*)&bias[col];
            float v0x = alpha * (acc[mi][ni][0] + b2.x);
            float v0y = alpha * (acc[mi][ni][1] + b2.y);
            float v1x = alpha * (acc[mi][ni][2] + b2.x);
            float v1y = alpha * (acc[mi][ni][3] + b2.y);
            size_t p0 = (size_t)row * DMODEL + col;
            size_t p1 = (size_t)(row + 8) * DMODEL + col;
            if (C) {
                *(float2*)&C[p0] = make_float2(v0x, v0y);
                *(float2*)&C[p1] = make_float2(v1x, v1y);
            }
            if (Chi) {
                *(uint32_t*)&Chi[p0] = pack_h(v0x, v0y);
                *(uint32_t*)&Chi[p1] = pack_h(v1x, v1y);
            }
        }
    }
}

// 3 projection GEMMs in one launch (gridDim.z = 3)
__global__ __launch_bounds__(256, 2)
void gemm_mma3(const __half* __restrict__ act3, const __half* __restrict__ w4,
               const float* __restrict__ bq, const float* __restrict__ bk,
               const float* __restrict__ bv,
               __half* __restrict__ qh, __half* __restrict__ kh,
               __half* __restrict__ vh)
{
    extern __shared__ char smem[];
    const int z = blockIdx.z;
    const __half* A = act3 + (size_t)z * MROWS * DMODEL;
    const __half* W = w4 + (size_t)z * DMODEL * DMODEL;
    const float* bias = (z == 0) ? bq : (z == 1) ? bk : bv;
    __half* Chi = (z == 0) ? qh : (z == 1) ? kh : vh;
    float alpha = (z == 0) ? 0.125f : 1.0f;
    gemm_body(A, W, bias, (float*)0, Chi, alpha, smem);
}

// single GEMM (output projection)
__global__ __launch_bounds__(256, 2)
void gemm_mma(const __half* __restrict__ A, const __half* __restrict__ W,
              const float* __restrict__ bias, float* __restrict__ C,
              __half* __restrict__ Chi, float alpha)
{
    extern __shared__ char smem[];
    gemm_body(A, W, bias, C, Chi, alpha, smem);
}

// ---------------------------------------------------------------------------
// Fused HMMA attention v6 (unchanged from R15, passing): QT=32, 512 threads,
// 4-stage cp.async ring, PV with no reduction.
// ---------------------------------------------------------------------------
#define QT 32
#define O_SC   0
#define O_QH   131072
#define O_KB   135680
#define KSTG   18432
#define O_PEK  209408
#define O_PEV  211712
#define O_RB   214016
#define O_WS   215552
#define O_MSK  217088
#define ATT_SMEM 218112

__global__ __launch_bounds__(512, 1)
void attn_mma(const __half* __restrict__ qh,
              const __half* __restrict__ kh, const __half* __restrict__ vh,
              const int* __restrict__ mask, const float* __restrict__ pe_k,
              const float* __restrict__ pe_v, float* __restrict__ attn_out,
              __half* __restrict__ Oh)
{
    extern __shared__ char smem[];
    const uint32_t sb = smem_u32(smem);
    float* sc = (float*)smem;
    __half* QH = (__half*)(smem + O_QH);
    float* pek = (float*)(smem + O_PEK);
    float* pev = (float*)(smem + O_PEV);
    float* rb  = (float*)(smem + O_RB);
    float* ws  = (float*)(smem + O_WS);
    unsigned char* msk = (unsigned char*)(smem + O_MSK);

    const int b  = blockIdx.z;
    const int h  = blockIdx.y;
    const int qb = blockIdx.x * QT;
    const int tid = threadIdx.x;
    const int w = tid >> 5;
    const int lane = tid & 31;
    const int lr = lane >> 2;
    const int lc = lane & 3;

    const int liR0 = tid >> 3, liD0 = tid & 7;
    const int liR1 = (tid + 512) >> 3, liD1 = tid & 7;

#define ISSUE_T(SRC, TB, ST) do {                                              \
    uint32_t sd = sb + O_KB + (ST) * KSTG;                                     \
    size_t gA = (size_t)(b * S_LEN + (TB) * 128 + liR0) * DMODEL               \
              + h * DHEAD + liD0 * 8;                                          \
    size_t gB = (size_t)(b * S_LEN + (TB) * 128 + liR1) * DMODEL               \
              + h * DHEAD + liD1 * 8;                                          \
    cp_async16(sd + (uint32_t)(liR0 * 72 + liD0 * 8) * 2, (SRC) + gA);         \
    cp_async16(sd + (uint32_t)(liR1 * 72 + liD1 * 8) * 2, (SRC) + gB);         \
} while (0)

    ISSUE_T(kh, 0, 0); CP_COMMIT;
    ISSUE_T(kh, 1, 1); CP_COMMIT;
    ISSUE_T(kh, 2, 2); CP_COMMIT;

    if (tid < 256) {
        int row = tid >> 3, dg = tid & 7;
        size_t g = (size_t)(b * S_LEN + qb + row) * DMODEL + h * DHEAD + dg * 8;
        *(uint4*)&QH[row * 72 + dg * 8] = *(const uint4*)&qh[g];
    }
    for (int i = tid; i < 576; i += 512) { pek[i] = pe_k[i]; pev[i] = pe_v[i]; }
    for (int i = tid; i < S_LEN; i += 512)
        msk[i] = (unsigned char)(mask[b * S_LEN + i] != 0);
    __syncthreads();

    for (int i = tid; i < QT * 9; i += 512) {
        int qi = i / 9, j = i % 9;
        float s = 0.f;
        const __half* qhr = QH + qi * 72;
        const float* pr = pek + j * 64;
#pragma unroll 16
        for (int d = 0; d < 64; d++)
            s += __half2float(qhr[d]) * pr[d];
        rb[qi * 12 + j] = s;
    }

    uint32_t qah[4][2][4];
#pragma unroll
    for (int ks = 0; ks < 4; ks++)
#pragma unroll
        for (int mt = 0; mt < 2; mt++) {
            int r = mt * 16 + lr;
            int kc = ks * 16 + lc * 2;
            qah[ks][mt][0] = *(const uint32_t*)&QH[r * 72 + kc];
            qah[ks][mt][1] = *(const uint32_t*)&QH[(r + 8) * 72 + kc];
            qah[ks][mt][2] = *(const uint32_t*)&QH[r * 72 + kc + 8];
            qah[ks][mt][3] = *(const uint32_t*)&QH[(r + 8) * 72 + kc + 8];
        }

    // ---- scores: 8 tiles of 128 k-cols; ring ----
    const int n0 = w * 8;
    for (int kb = 0; kb < 8; kb++) {
        CP_WAIT2;
        __syncthreads();

        const uint32_t kt = sb + O_KB + (kb & 3) * KSTG;
        uint32_t bh2[2][4];
#pragma unroll
        for (int j = 0; j < 2; j++) {
            uint32_t addr = kt + (uint32_t)(n0 + (lane & 7)) * 144
                          + j * 64 + (lane >> 3) * 16;
            ldmx4(bh2[j], addr);
        }

        {
            int t = kb + 3;
            if (t < 8) { ISSUE_T(kh, t, t & 3); }
            else       { ISSUE_T(vh, t - 8, t & 3); }
            CP_COMMIT;
        }

        float c[2][4] = {{0.f,0.f,0.f,0.f},{0.f,0.f,0.f,0.f}};
#pragma unroll
        for (int ks = 0; ks < 4; ks++) {
            uint32_t* bh = &bh2[ks >> 1][(ks & 1) * 2];
#pragma unroll
            for (int mt = 0; mt < 2; mt++)
                mma16816(c[mt], qah[ks][mt], bh);
        }
#pragma unroll
        for (int mt = 0; mt < 2; mt++) {
#pragma unroll
            for (int half = 0; half < 2; half++) {
                int qi = mt * 16 + lr + half * 8;
                int qg = qb + qi;
                int kg = kb * 128 + n0 + lc * 2;
                float v0 = c[mt][half * 2 + 0];
                float v1 = c[mt][half * 2 + 1];
                int d0 = min(MAXK, max(-MAXK, kg - qg)) + MAXK;
                int d1 = min(MAXK, max(-MAXK, kg + 1 - qg)) + MAXK;
                v0 = msk[kg] ? v0 + rb[qi * 12 + d0] : -INFINITY;
                v1 = msk[kg + 1] ? v1 + rb[qi * 12 + d1] : -INFINITY;
                *(float2*)&sc[qi * S_LEN + kg] = make_float2(v0, v1);
            }
        }
    }
    __syncthreads();

    // ---- softmax: warp w -> rows 2w, 2w+1 ----
#pragma unroll
    for (int r = 0; r < 2; r++) {
        int qi = w * 2 + r;
        int qg = qb + qi;
        float* row = sc + qi * S_LEN;

        float m = -INFINITY;
        for (int k2 = lane; k2 < S_LEN; k2 += 32) m = fmaxf(m, row[k2]);
#pragma unroll
        for (int o = 16; o; o >>= 1) m = fmaxf(m, __shfl_xor_sync(0xFFFFFFFFu, m, o));

        float sum = 0.f;
        for (int k2 = lane; k2 < S_LEN; k2 += 32) {
            float e = __expf(row[k2] - m);
            row[k2] = e;
            sum += e;
        }
#pragma unroll
        for (int o = 16; o; o >>= 1) sum += __shfl_xor_sync(0xFFFFFFFFu, sum, o);
        float inv = 1.f / sum;

        float* ao = attn_out ? attn_out + ((size_t)(b * NHEAD + h) * S_LEN + qg) * S_LEN
                             : (float*)0;
        float w0 = 0.f, w8 = 0.f;
        for (int k2 = lane; k2 < S_LEN; k2 += 32) {
            float p = row[k2] * inv;
            row[k2] = p;
            if (ao) ao[k2] = p;
            if (k2 <= qg - MAXK) w0 += p;
            if (k2 >= qg + MAXK) w8 += p;
        }
#pragma unroll
        for (int o = 16; o; o >>= 1) {
            w0 += __shfl_xor_sync(0xFFFFFFFFu, w0, o);
            w8 += __shfl_xor_sync(0xFFFFFFFFu, w8, o);
        }
        __syncwarp();
        if (lane == 0) { ws[qi * 12 + 0] = w0; ws[qi * 12 + 8] = w8; }
        if (lane >= 1 && lane <= 7) {
            int k2 = qg + lane - MAXK;
            ws[qi * 12 + lane] = (k2 >= 0 && k2 < S_LEN) ? row[k2] : 0.f;
        }
        __syncwarp();

        float x[32];
#pragma unroll
        for (int t = 0; t < 16; t++) {
            float2 v = *(const float2*)(row + 2 * (lane + 32 * t));
            x[2 * t] = v.x;
            x[2 * t + 1] = v.y;
        }
        __syncwarp();
        uint32_t swz = (uint32_t)((qi & 7) << 4);
        char* rowb = smem + qi * 4096;
#pragma unroll
        for (int t = 0; t < 16; t++) {
            int j = lane + 32 * t;
            *(uint32_t*)(rowb + (((uint32_t)(4 * j)) ^ swz)) =
                pack_h(x[2 * t], x[2 * t + 1]);
        }
    }

    // ---- PV: warp (mw, wn) owns m-tile mw, d-cols wn*8..+7 ----
    const int mw = w >> 3;
    const int wn = w & 7;
    float o[4] = {0.f, 0.f, 0.f, 0.f};
    const int prow = mw * 16 + (lane & 7) + ((lane >> 3) & 1) * 8;
    const uint32_t pswz = (uint32_t)((prow & 7) << 4);

    for (int vb = 0; vb < 8; vb++) {
        CP_WAIT2;
        __syncthreads();

        const uint32_t vtile = sb + O_KB + (vb & 3) * KSTG;
        uint32_t vbh[4][4];
#pragma unroll
        for (int j = 0; j < 4; j++) {
            uint32_t addr = vtile + (uint32_t)(j * 32 + lane) * 144 + wn * 16;
            ldmx4t(vbh[j], addr);
        }

        if (vb + 3 < 8) { ISSUE_T(vh, vb + 3, (vb + 3) & 3); }
        CP_COMMIT;

#pragma unroll
        for (int ks = 0; ks < 8; ks++) {
            uint32_t cby = (uint32_t)(vb * 256 + ks * 32 + (lane >> 4) * 16) ^ pswz;
            uint32_t a[4];
            ldmx4(a, sb + (uint32_t)prow * 4096 + cby);
            mma16816(o, a, &vbh[ks >> 1][(ks & 1) * 2]);
        }
    }

    // ---- epilogue: rel_v + write O ----
#pragma unroll
    for (int half = 0; half < 2; half++) {
        int qi = mw * 16 + lr + half * 8;
        int d0 = wn * 8 + lc * 2;
        float a0 = o[half * 2 + 0];
        float a1 = o[half * 2 + 1];
#pragma unroll
        for (int j = 0; j < 9; j++) {
            float wv = ws[qi * 12 + j];
            a0 += wv * pev[j * 64 + d0];
            a1 += wv * pev[j * 64 + d0 + 1];
        }
        size_t base = (size_t)(b * S_LEN + qb + qi) * DMODEL + h * DHEAD + d0;
        *(uint32_t*)&Oh[base] = pack_h(a0, a1);
    }
}

// ---------------------------------------------------------------------------
extern "C" void kernel_launch(void* const* d_in, const int* in_sizes, int n_in,
                              void* d_out, int out_size)
{
    const float* query = (const float*)d_in[0];
    const float* key   = (const float*)d_in[1];
    const float* value = (const float*)d_in[2];
    const int*   mask  = (const int*)d_in[3];
    const float* Wq = (const float*)d_in[4];
    const float* bq = (const float*)d_in[5];
    const float* Wk = (const float*)d_in[6];
    const float* bk = (const float*)d_in[7];
    const float* Wv = (const float*)d_in[8];
    const float* bv = (const float*)d_in[9];
    const float* Wo = (const float*)d_in[10];
    const float* bo = (const float*)d_in[11];
    const float* pe_k = (const float*)d_in[12];
    const float* pe_v = (const float*)d_in[13];

    __half *act3, *w4, *qh, *kh, *vh, *oh;
    cudaGetSymbolAddress((void**)&act3, g_act3);
    cudaGetSymbolAddress((void**)&w4, g_w4);
    cudaGetSymbolAddress((void**)&qh, g_qh);
    cudaGetSymbolAddress((void**)&kh, g_kh);
    cudaGetSymbolAddress((void**)&vh, g_vh);
    cudaGetSymbolAddress((void**)&oh, g_oh);

    const long long OUT_ELEMS = (long long)BATCH * S_LEN * DMODEL;
    float* out_ptr  = (float*)d_out;
    float* attn_ptr = ((long long)out_size > OUT_ELEMS) ? (float*)d_out + OUT_ELEMS
                                                        : (float*)0;

    cudaFuncSetAttribute(attn_mma, cudaFuncAttributeMaxDynamicSharedMemorySize,
                         ATT_SMEM);
    cudaFuncSetAttribute(gemm_mma, cudaFuncAttributeMaxDynamicSharedMemorySize,
                         GEMM_SMEM);
    cudaFuncSetAttribute(gemm_mma3, cudaFuncAttributeMaxDynamicSharedMemorySize,
                         GEMM_SMEM);

    // one launch for all 7 converts
    conv_all_kernel<<<TOT4 / 512, 256>>>(query, key, value, Wq, Wk, Wv, Wo,
                                         act3, w4);

    // Q/K/V projections in one launch (z selects; 1/SCALE folded into Q)
    dim3 gg3(DMODEL / 128, MROWS / 128, 3);
    gemm_mma3<<<gg3, 256, GEMM_SMEM>>>(act3, w4, bq, bk, bv, qh, kh, vh);

    // fused attention
    dim3 ga(S_LEN / QT, NHEAD, BATCH);   // (32, 16, 8)
    attn_mma<<<ga, 512, ATT_SMEM>>>(qh, kh, vh, mask, pe_k, pe_v, attn_ptr, oh);

    // output projection (fp32 out)
    dim3 gg(DMODEL / 128, MROWS / 128);
    gemm_mma<<<gg, 256, GEMM_SMEM>>>(oh, w4 + 3 * (size_t)DMODEL * DMODEL, bo,
                                     out_ptr, (__half*)0, 1.0f);
}